// round 14
// baseline (speedup 1.0000x reference)
#include <cuda_runtime.h>
#include <cuda_bf16.h>
#include <cstdint>

#define N_NODES_MAX 100000
#define MASK_WORDS ((N_NODES_MAX + 31) / 32)
#define DSIGMA_DT (-0.0001f)
#define PHI_THRESH 0.3f
#define EPS 1e-8f

// Packed {pos.x, pos.y, pos.z, T}; accumulator {num.xyz, cnt}; mask bitmap.
__device__ float4 g_packed[N_NODES_MAX];
__device__ float4 g_acc[N_NODES_MAX];
__device__ unsigned g_mask[MASK_WORDS];
__device__ int g_idx_is64;

// Prep + L2-prefetch kernel. Blocks [0, node_blocks): R8 prep body.
// Blocks [node_blocks, gridDim): stream-prefetch the edge_index array into
// L2 (fire-and-forget) so the edge kernel's index reads hit L2 instead of
// DRAM. Each prefetch block re-derives the dtype locally (no race on the
// global flag) and never prefetches past the real allocation.
__global__ __launch_bounds__(256) void prep_kernel(
        const float* __restrict__ x,
        const float* __restrict__ pos,
        const void* __restrict__ edge_index,
        int n_nodes, int n_edges, int node_blocks) {
    const int tid = threadIdx.x;

    if ((int)blockIdx.x < node_blocks) {
        int i = blockIdx.x * 256 + tid;
        unsigned bit = 0;
        if (i < n_nodes) {
            float p0 = __ldg(&pos[i * 3 + 0]);
            float p1 = __ldg(&pos[i * 3 + 1]);
            float p2 = __ldg(&pos[i * 3 + 2]);
            float t  = __ldg(&x[i * 9 + 3]);
            float phi = __ldg(&x[i * 9 + 8]);
            g_packed[i] = make_float4(p0, p1, p2, t);
            g_acc[i] = make_float4(0.f, 0.f, 0.f, 0.f);
            bit = (fabsf(phi) < PHI_THRESH) ? 1u : 0u;
        }
        unsigned word = __ballot_sync(0xFFFFFFFFu, bit);
        if ((tid & 31) == 0 && i < n_nodes) g_mask[i >> 5] = word;

        if (blockIdx.x == 0 && tid == 0) {
            // int64 LE with values < 2^31 => odd 32-bit words all zero.
            const unsigned int* w = (const unsigned int*)edge_index;
            unsigned int acc = 0;
            #pragma unroll
            for (int k = 0; k < 64; k++) acc |= w[2 * k + 1];
            g_idx_is64 = (acc == 0) ? 1 : 0;
        }
    } else {
        // ── prefetch role ──
        // Local dtype detection (cheap; avoids racing the global flag).
        const unsigned int* w = (const unsigned int*)edge_index;
        unsigned int acc = 0;
        #pragma unroll
        for (int k = 0; k < 64; k++) acc |= w[2 * k + 1];
        int is64 = (acc == 0) ? 1 : 0;

        size_t total_bytes = (size_t)(2 * n_edges) * (is64 ? 8u : 4u);
        int pref_blocks = gridDim.x - node_blocks;
        int pt = (blockIdx.x - node_blocks) * 256 + tid;
        size_t stride = (size_t)pref_blocks * 256u * 128u;
        const char* base = (const char*)edge_index;
        for (size_t off = (size_t)pt * 128u; off < total_bytes; off += stride) {
            asm volatile("prefetch.global.L2 [%0];" :: "l"(base + off));
        }
    }
}

// Grid-stride edge scatter (R8 body): __ldcs index stream, smem mask bitmap,
// ~76% of edges skipped, one RED.v4.f32 per live edge.
__global__ __launch_bounds__(512) void edge_scatter_kernel(
        const void* __restrict__ edge_index, int n_edges, int mask_words) {
    __shared__ unsigned smask[MASK_WORDS];
    for (int w = threadIdx.x; w < mask_words; w += blockDim.x)
        smask[w] = g_mask[w];
    __syncthreads();

    const int stride = gridDim.x * blockDim.x;
    const int start = blockIdx.x * blockDim.x + threadIdx.x;

    if (g_idx_is64) {
        const long long* ei = (const long long*)edge_index;
        for (int e = start; e < n_edges; e += stride) {
            int d = (int)__ldcs(&ei[n_edges + e]);
            if ((smask[d >> 5] >> (d & 31)) & 1u) {
                int s = (int)__ldcs(&ei[e]);
                float4 a = __ldg(&g_packed[s]);
                float4 b = __ldg(&g_packed[d]);
                float dT = a.w - b.w;
                float px = a.x - b.x, py = a.y - b.y, pz = a.z - b.z;
                float w = dT / (px * px + py * py + pz * pz + EPS);
                float4* addr = &g_acc[d];
                asm volatile("red.global.add.v4.f32 [%0], {%1, %2, %3, %4};"
                             :: "l"(addr), "f"(w * px), "f"(w * py), "f"(w * pz), "f"(1.0f)
                             : "memory");
            }
        }
    } else {
        const int* ei = (const int*)edge_index;
        for (int e = start; e < n_edges; e += stride) {
            int d = __ldcs(&ei[n_edges + e]);
            if ((smask[d >> 5] >> (d & 31)) & 1u) {
                int s = __ldcs(&ei[e]);
                float4 a = __ldg(&g_packed[s]);
                float4 b = __ldg(&g_packed[d]);
                float dT = a.w - b.w;
                float px = a.x - b.x, py = a.y - b.y, pz = a.z - b.z;
                float w = dT / (px * px + py * py + pz * pz + EPS);
                float4* addr = &g_acc[d];
                asm volatile("red.global.add.v4.f32 [%0], {%1, %2, %3, %4};"
                             :: "l"(addr), "f"(w * px), "f"(w * py), "f"(w * pz), "f"(1.0f)
                             : "memory");
            }
        }
    }
}

__global__ __launch_bounds__(256) void finalize_kernel(
        float* __restrict__ out, int n_nodes) {
    int i = blockIdx.x * blockDim.x + threadIdx.x;
    if (i >= n_nodes) return;

    unsigned bit = (g_mask[i >> 5] >> (i & 31)) & 1u;
    float4 a = g_acc[i];

    float cnt = fmaxf(a.w, 1.0f);
    float s = bit ? (DSIGMA_DT / cnt) : 0.0f;

    out[i * 3 + 0] = s * a.x;
    out[i * 3 + 1] = s * a.y;
    out[i * 3 + 2] = s * a.z;
}

extern "C" void kernel_launch(void* const* d_in, const int* in_sizes, int n_in,
                              void* d_out, int out_size) {
    const float* x = (const float*)d_in[0];    // [N, 9]
    const float* pos = (const float*)d_in[1];  // [N, 3]
    const void* edge_index = d_in[2];          // [2, E] int32 or int64

    int n_nodes = in_sizes[1] / 3;
    int n_edges = in_sizes[2] / 2;
    int mask_words = (n_nodes + 31) / 32;
    float* out = (float*)d_out;

    int node_blocks = (n_nodes + 255) / 256;   // 391
    int pref_blocks = 400;                     // ~102k prefetch threads
    prep_kernel<<<node_blocks + pref_blocks, 256>>>(
        x, pos, edge_index, n_nodes, n_edges, node_blocks);

    int eblocks = (n_edges + 511) / 512;
    if (eblocks > 592) eblocks = 592;          // ~4 blocks/SM, grid-stride
    edge_scatter_kernel<<<eblocks, 512>>>(edge_index, n_edges, mask_words);

    finalize_kernel<<<(n_nodes + 255) / 256, 256>>>(out, n_nodes);
}

// round 15
// speedup vs baseline: 1.1910x; 1.1910x over previous
#include <cuda_runtime.h>
#include <cuda_bf16.h>
#include <cstdint>

#define N_NODES_MAX 100000
#define MASK_WORDS ((N_NODES_MAX + 31) / 32)
#define DSIGMA_DT (-0.0001f)
#define PHI_THRESH 0.3f
#define EPS 1e-8f

// Packed {pos.x, pos.y, pos.z, T} per node; accumulator {num.xyz, cnt};
// interface-mask bitmap (1 bit per node).
__device__ float4 g_packed[N_NODES_MAX];
__device__ float4 g_acc[N_NODES_MAX];
__device__ unsigned g_mask[MASK_WORDS];
__device__ int g_idx_is64;

// Per-node: pack {pos,T}, zero acc, build mask bitmap via ballot, detect dtype.
// (Exact R8 body — proven fastest; prep is latency-floor bound.)
__global__ __launch_bounds__(256) void prep_kernel(
        const float* __restrict__ x,
        const float* __restrict__ pos,
        const unsigned int* __restrict__ ei_words,
        int n_nodes) {
    int i = blockIdx.x * blockDim.x + threadIdx.x;
    bool active = (i < n_nodes);

    unsigned bit = 0;
    if (active) {
        float p0 = __ldg(&pos[i * 3 + 0]);
        float p1 = __ldg(&pos[i * 3 + 1]);
        float p2 = __ldg(&pos[i * 3 + 2]);
        float t  = __ldg(&x[i * 9 + 3]);
        float phi = __ldg(&x[i * 9 + 8]);
        g_packed[i] = make_float4(p0, p1, p2, t);
        g_acc[i] = make_float4(0.f, 0.f, 0.f, 0.f);
        bit = (fabsf(phi) < PHI_THRESH) ? 1u : 0u;
    }
    unsigned word = __ballot_sync(0xFFFFFFFFu, bit);
    if ((threadIdx.x & 31) == 0 && i < n_nodes) {
        g_mask[i >> 5] = word;
    }

    if (i == 0) {
        // int64 little-endian with values < 2^31 => odd 32-bit words all zero.
        unsigned int acc = 0;
        #pragma unroll
        for (int k = 0; k < 64; k++) acc |= ei_words[2 * k + 1];
        g_idx_is64 = (acc == 0) ? 1 : 0;
    }
}

// Grid-stride edge scatter (R8 inner loop): __ldcs index stream (evict-first
// protects hot node tables in L2), smem mask bitmap, ~76% of edges skipped,
// one RED.v4.f32 per live edge. TPB=1024 / 296 blocks: same occupancy as
// 512/592 but half the per-block mask-staging + ramp overhead.
__global__ __launch_bounds__(1024) void edge_scatter_kernel(
        const void* __restrict__ edge_index, int n_edges, int mask_words) {
    __shared__ unsigned smask[MASK_WORDS];
    for (int w = threadIdx.x; w < mask_words; w += blockDim.x)
        smask[w] = g_mask[w];
    __syncthreads();

    const int stride = gridDim.x * blockDim.x;
    const int start = blockIdx.x * blockDim.x + threadIdx.x;

    if (g_idx_is64) {
        const long long* ei = (const long long*)edge_index;
        for (int e = start; e < n_edges; e += stride) {
            int d = (int)__ldcs(&ei[n_edges + e]);
            if ((smask[d >> 5] >> (d & 31)) & 1u) {
                int s = (int)__ldcs(&ei[e]);
                float4 a = __ldg(&g_packed[s]);
                float4 b = __ldg(&g_packed[d]);
                float dT = a.w - b.w;
                float px = a.x - b.x, py = a.y - b.y, pz = a.z - b.z;
                float w = dT / (px * px + py * py + pz * pz + EPS);
                float4* addr = &g_acc[d];
                asm volatile("red.global.add.v4.f32 [%0], {%1, %2, %3, %4};"
                             :: "l"(addr), "f"(w * px), "f"(w * py), "f"(w * pz), "f"(1.0f)
                             : "memory");
            }
        }
    } else {
        const int* ei = (const int*)edge_index;
        for (int e = start; e < n_edges; e += stride) {
            int d = __ldcs(&ei[n_edges + e]);
            if ((smask[d >> 5] >> (d & 31)) & 1u) {
                int s = __ldcs(&ei[e]);
                float4 a = __ldg(&g_packed[s]);
                float4 b = __ldg(&g_packed[d]);
                float dT = a.w - b.w;
                float px = a.x - b.x, py = a.y - b.y, pz = a.z - b.z;
                float w = dT / (px * px + py * py + pz * pz + EPS);
                float4* addr = &g_acc[d];
                asm volatile("red.global.add.v4.f32 [%0], {%1, %2, %3, %4};"
                             :: "l"(addr), "f"(w * px), "f"(w * py), "f"(w * pz), "f"(1.0f)
                             : "memory");
            }
        }
    }
}

__global__ __launch_bounds__(256) void finalize_kernel(
        float* __restrict__ out, int n_nodes) {
    int i = blockIdx.x * blockDim.x + threadIdx.x;
    if (i >= n_nodes) return;

    unsigned bit = (g_mask[i >> 5] >> (i & 31)) & 1u;
    float4 a = g_acc[i];

    float cnt = fmaxf(a.w, 1.0f);
    float s = bit ? (DSIGMA_DT / cnt) : 0.0f;

    out[i * 3 + 0] = s * a.x;
    out[i * 3 + 1] = s * a.y;
    out[i * 3 + 2] = s * a.z;
}

extern "C" void kernel_launch(void* const* d_in, const int* in_sizes, int n_in,
                              void* d_out, int out_size) {
    const float* x = (const float*)d_in[0];    // [N, 9]
    const float* pos = (const float*)d_in[1];  // [N, 3]
    const void* edge_index = d_in[2];          // [2, E] int32 or int64

    int n_nodes = in_sizes[1] / 3;
    int n_edges = in_sizes[2] / 2;
    int mask_words = (n_nodes + 31) / 32;
    float* out = (float*)d_out;

    prep_kernel<<<(n_nodes + 255) / 256, 256>>>(
        x, pos, (const unsigned int*)edge_index, n_nodes);

    int eblocks = (n_edges + 1023) / 1024;
    if (eblocks > 296) eblocks = 296;   // 2 blocks/SM x 1024 = full occupancy
    edge_scatter_kernel<<<eblocks, 1024>>>(edge_index, n_edges, mask_words);

    finalize_kernel<<<(n_nodes + 255) / 256, 256>>>(out, n_nodes);
}

// round 17
// speedup vs baseline: 1.2092x; 1.0153x over previous
#include <cuda_runtime.h>
#include <cuda_bf16.h>
#include <cstdint>

#define N_NODES_MAX 100000
#define MASK_WORDS ((N_NODES_MAX + 31) / 32)
#define DSIGMA_DT (-0.0001f)
#define PHI_THRESH 0.3f
#define EPS 1e-8f

// Packed {pos.x, pos.y, pos.z, T} per node; accumulator {num.xyz, cnt}
// (zero at module load; finalize re-zeroes live nodes each execution, dead
// nodes never receive REDs so they stay zero); interface-mask bitmap.
__device__ float4 g_packed[N_NODES_MAX];
__device__ float4 g_acc[N_NODES_MAX];
__device__ unsigned g_mask[MASK_WORDS];
__device__ int g_idx_is64;

// Per-node pack {pos,T} + mask bitmap + dtype detect. No acc zeroing (moved
// to finalize). TPB=1024: same 100k threads, 1/4 the blocks -> less ramp.
__global__ __launch_bounds__(1024) void prep_kernel(
        const float* __restrict__ x,
        const float* __restrict__ pos,
        const unsigned int* __restrict__ ei_words,
        int n_nodes) {
    int i = blockIdx.x * blockDim.x + threadIdx.x;

    unsigned bit = 0;
    if (i < n_nodes) {
        float p0 = __ldg(&pos[i * 3 + 0]);
        float p1 = __ldg(&pos[i * 3 + 1]);
        float p2 = __ldg(&pos[i * 3 + 2]);
        float t  = __ldg(&x[i * 9 + 3]);
        float phi = __ldg(&x[i * 9 + 8]);
        g_packed[i] = make_float4(p0, p1, p2, t);
        bit = (fabsf(phi) < PHI_THRESH) ? 1u : 0u;
    }
    unsigned word = __ballot_sync(0xFFFFFFFFu, bit);
    if ((threadIdx.x & 31) == 0 && i < n_nodes) {
        g_mask[i >> 5] = word;
    }

    if (i == 0) {
        // int64 little-endian with values < 2^31 => odd 32-bit words all zero.
        unsigned int acc = 0;
        #pragma unroll
        for (int k = 0; k < 64; k++) acc |= ei_words[2 * k + 1];
        g_idx_is64 = (acc == 0) ? 1 : 0;
    }
}

// Grid-stride edge scatter (exact R15 config): __ldcs index stream, smem mask
// bitmap, ~76% of edges skipped, one RED.v4.f32 per live edge.
// TPB=1024 / 296 blocks = full occupancy with minimal per-block overhead.
__global__ __launch_bounds__(1024) void edge_scatter_kernel(
        const void* __restrict__ edge_index, int n_edges, int mask_words) {
    __shared__ unsigned smask[MASK_WORDS];
    for (int w = threadIdx.x; w < mask_words; w += blockDim.x)
        smask[w] = g_mask[w];
    __syncthreads();

    const int stride = gridDim.x * blockDim.x;
    const int start = blockIdx.x * blockDim.x + threadIdx.x;

    if (g_idx_is64) {
        const long long* ei = (const long long*)edge_index;
        for (int e = start; e < n_edges; e += stride) {
            int d = (int)__ldcs(&ei[n_edges + e]);
            if ((smask[d >> 5] >> (d & 31)) & 1u) {
                int s = (int)__ldcs(&ei[e]);
                float4 a = __ldg(&g_packed[s]);
                float4 b = __ldg(&g_packed[d]);
                float dT = a.w - b.w;
                float px = a.x - b.x, py = a.y - b.y, pz = a.z - b.z;
                float w = dT / (px * px + py * py + pz * pz + EPS);
                float4* addr = &g_acc[d];
                asm volatile("red.global.add.v4.f32 [%0], {%1, %2, %3, %4};"
                             :: "l"(addr), "f"(w * px), "f"(w * py), "f"(w * pz), "f"(1.0f)
                             : "memory");
            }
        }
    } else {
        const int* ei = (const int*)edge_index;
        for (int e = start; e < n_edges; e += stride) {
            int d = __ldcs(&ei[n_edges + e]);
            if ((smask[d >> 5] >> (d & 31)) & 1u) {
                int s = __ldcs(&ei[e]);
                float4 a = __ldg(&g_packed[s]);
                float4 b = __ldg(&g_packed[d]);
                float dT = a.w - b.w;
                float px = a.x - b.x, py = a.y - b.y, pz = a.z - b.z;
                float w = dT / (px * px + py * py + pz * pz + EPS);
                float4* addr = &g_acc[d];
                asm volatile("red.global.add.v4.f32 [%0], {%1, %2, %3, %4};"
                             :: "l"(addr), "f"(w * px), "f"(w * py), "f"(w * pz), "f"(1.0f)
                             : "memory");
            }
        }
    }
}

// Finalize + reset: write output, then zero acc for live nodes (dead nodes
// never accumulate). TPB=1024 -> 98 blocks.
__global__ __launch_bounds__(1024) void finalize_kernel(
        float* __restrict__ out, int n_nodes) {
    int i = blockIdx.x * blockDim.x + threadIdx.x;
    if (i >= n_nodes) return;

    unsigned bit = (g_mask[i >> 5] >> (i & 31)) & 1u;
    float4 a = g_acc[i];

    float cnt = fmaxf(a.w, 1.0f);
    float s = bit ? (DSIGMA_DT / cnt) : 0.0f;

    out[i * 3 + 0] = s * a.x;
    out[i * 3 + 1] = s * a.y;
    out[i * 3 + 2] = s * a.z;

    if (bit) g_acc[i] = make_float4(0.f, 0.f, 0.f, 0.f);
}

extern "C" void kernel_launch(void* const* d_in, const int* in_sizes, int n_in,
                              void* d_out, int out_size) {
    const float* x = (const float*)d_in[0];    // [N, 9]
    const float* pos = (const float*)d_in[1];  // [N, 3]
    const void* edge_index = d_in[2];          // [2, E] int32 or int64

    int n_nodes = in_sizes[1] / 3;
    int n_edges = in_sizes[2] / 2;
    int mask_words = (n_nodes + 31) / 32;
    float* out = (float*)d_out;

    prep_kernel<<<(n_nodes + 1023) / 1024, 1024>>>(
        x, pos, (const unsigned int*)edge_index, n_nodes);

    int eblocks = (n_edges + 1023) / 1024;
    if (eblocks > 296) eblocks = 296;   // 2 blocks/SM x 1024 = full occupancy
    edge_scatter_kernel<<<eblocks, 1024>>>(edge_index, n_edges, mask_words);

    finalize_kernel<<<(n_nodes + 1023) / 1024, 1024>>>(out, n_nodes);
}